// round 7
// baseline (speedup 1.0000x reference)
#include <cuda_runtime.h>
#include <math.h>

#define NB   2048
#define NT   200
#define NE   64
#define NH1  64
#define NH2  16
#define NROWS (NB*NT)

// Scratch (device globals; no allocation allowed)
__device__ float g_x2[(size_t)NROWS * NH2];   // [B*T, 16]
__device__ float g_sum1[NH1], g_sq1[NH1];
__device__ float g_sum2[NH2], g_sq2[NH2];

__device__ __forceinline__ unsigned tf32_of(float f) {
    unsigned r;
    asm("cvt.rna.tf32.f32 %0, %1;" : "=r"(r) : "f"(f));
    return r;
}
__device__ __forceinline__ void tf32_split(float a, unsigned& hi, unsigned& lo) {
    hi = tf32_of(a);
    lo = tf32_of(a - __uint_as_float(hi));
}

#define MMA_TF32(d, a0,a1,a2,a3, b0,b1) \
    asm("mma.sync.aligned.m16n8k8.row.col.f32.tf32.tf32.f32 " \
        "{%0,%1,%2,%3}, {%4,%5,%6,%7}, {%8,%9}, {%0,%1,%2,%3};" \
        : "+f"(d[0]), "+f"(d[1]), "+f"(d[2]), "+f"(d[3]) \
        : "r"(a0), "r"(a1), "r"(a2), "r"(a3), "r"(b0), "r"(b1))

__global__ void k_zero() {
    int i = threadIdx.x;
    if (i < NH1) { g_sum1[i] = 0.f; g_sq1[i] = 0.f; }
    if (i < NH2) { g_sum2[i] = 0.f; g_sq2[i] = 0.f; }
}

// ---------------------------------------------------------------------------
// K1: stats of x1 = h@Wb + cb, no x1 store. 2-term TF32 (a-split x b-hi).
// 2 blocks per batch (rows 0..127 / 128..199).
// ---------------------------------------------------------------------------
__global__ __launch_bounds__(256, 3) void k_stats1(
    const float* __restrict__ q, const float* __restrict__ hist,
    const float* __restrict__ W1, const float* __restrict__ b1)
{
    extern __shared__ __align__(16) float dsm[];
    float* s_h   = dsm;                       // [128][68] fp32 hist rows
    float* s_WbH = dsm + 128*68;              // [64][72] tf32-hi of Wb (K-major)
    __shared__ float s_q[NE], s_cb[NH1], s_sum[NH1], s_sq[NH1];

    int bid = blockIdx.x, tid = threadIdx.x;
    int b = bid >> 1, half = bid & 1;
    int R0 = half ? 128 : 0;
    int ntile = half ? 5 : 8;

    if (tid < NE) {
        s_q[tid] = q[b*NE + tid];
        s_cb[tid] = b1[tid];
        s_sum[tid] = 0.f; s_sq[tid] = 0.f;
    }
    __syncthreads();

    #pragma unroll
    for (int i = 0; i < 16; i++) {
        int idx = tid + 256*i;
        int e = idx >> 6, j = idx & 63;
        float w = W1[(64+e)*64 + j] - W1[(128+e)*64 + j] + s_q[e]*W1[(192+e)*64 + j];
        s_WbH[e*72 + j] = __uint_as_float(tf32_of(w));
    }
    {
        int j = tid & 63, part = tid >> 6;
        float acc = 0.f;
        #pragma unroll
        for (int i = 0; i < 16; i++) {
            int e = part*16 + i;
            acc += s_q[e] * (W1[e*64 + j] + W1[(128+e)*64 + j]);
        }
        atomicAdd(&s_cb[j], acc);
    }
    #pragma unroll
    for (int i = 0; i < 8; i++) {
        int f4 = tid + 256*i;
        int r = f4 >> 4, e0 = (f4 & 15) << 2;
        int t = R0 + r;
        float4 v = (t < NT) ? *(const float4*)&hist[((size_t)(b*NT + t))*NE + e0]
                            : make_float4(0.f, 0.f, 0.f, 0.f);
        *(float4*)&s_h[r*68 + e0] = v;
    }
    __syncthreads();

    int w = tid >> 5, lane = tid & 31, g = lane >> 2, tin = lane & 3;
    if (w < ntile) {
        float d[8][4];
        #pragma unroll
        for (int j = 0; j < 8; j++)
            #pragma unroll
            for (int u = 0; u < 4; u++) d[j][u] = 0.f;

        int arow = (16*w + g)*68;
        #pragma unroll
        for (int kt = 0; kt < 8; kt++) {
            int k0 = kt*8;
            float a0f = s_h[arow + k0 + tin];
            float a1f = s_h[arow + 8*68 + k0 + tin];
            float a2f = s_h[arow + k0 + tin + 4];
            float a3f = s_h[arow + 8*68 + k0 + tin + 4];
            unsigned ah0,ah1,ah2,ah3, al0,al1,al2,al3;
            tf32_split(a0f, ah0, al0); tf32_split(a1f, ah1, al1);
            tf32_split(a2f, ah2, al2); tf32_split(a3f, ah3, al3);
            int bbase = (k0 + tin)*72 + g;
            #pragma unroll
            for (int j = 0; j < 8; j++) {
                unsigned bh0 = __float_as_uint(s_WbH[bbase + j*8]);
                unsigned bh1 = __float_as_uint(s_WbH[bbase + 4*72 + j*8]);
                MMA_TF32(d[j], ah0,ah1,ah2,ah3, bh0,bh1);
                MMA_TF32(d[j], al0,al1,al2,al3, bh0,bh1);
            }
        }

        int rB = R0 + 16*w + g + 8;
        bool okB = (rB < NT);
        #pragma unroll
        for (int j = 0; j < 8; j++) {
            int c0 = j*8 + tin*2;
            float cb0 = s_cb[c0], cb1 = s_cb[c0+1];
            float v0 = d[j][0] + cb0, v1 = d[j][1] + cb1;
            float v2 = d[j][2] + cb0, v3 = d[j][3] + cb1;
            float sc0 = v0, sc1 = v1, qc0 = v0*v0, qc1 = v1*v1;
            if (okB) { sc0 += v2; sc1 += v3; qc0 += v2*v2; qc1 += v3*v3; }
            #pragma unroll
            for (int off = 4; off <= 16; off <<= 1) {
                sc0 += __shfl_xor_sync(0xffffffffu, sc0, off);
                sc1 += __shfl_xor_sync(0xffffffffu, sc1, off);
                qc0 += __shfl_xor_sync(0xffffffffu, qc0, off);
                qc1 += __shfl_xor_sync(0xffffffffu, qc1, off);
            }
            if (lane < 4) {
                atomicAdd(&s_sum[c0],   sc0); atomicAdd(&s_sum[c0+1], sc1);
                atomicAdd(&s_sq[c0],    qc0); atomicAdd(&s_sq[c0+1],  qc1);
            }
        }
    }
    __syncthreads();
    if (tid < NH1) {
        atomicAdd(&g_sum1[tid], s_sum[tid]);
        atomicAdd(&g_sq1[tid],  s_sq[tid]);
    }
}

// ---------------------------------------------------------------------------
// K2: recompute x1 (full 3xTF32), dice1 in regs, round-trip through smem,
// gemm2 via MMA, store x2 + stats2. hist tile smem reused as diced-x tile;
// W2 planes overlaid into dead Wb region.
// ---------------------------------------------------------------------------
__global__ __launch_bounds__(256, 3) void k_fused(
    const float* __restrict__ q, const float* __restrict__ hist,
    const float* __restrict__ W1, const float* __restrict__ b1,
    const float* __restrict__ W2, const float* __restrict__ b2,
    const float* __restrict__ alpha1)
{
    extern __shared__ __align__(16) float dsm[];
    float* s_h   = dsm;                       // [128][68] hist, later diced x1
    float* s_WbH = dsm + 128*68;              // [64][72] tf32-hi Wb
    float* s_WbL = s_WbH + 64*72;             // [64][72] tf32-lo Wb
    float* s_W2TH = s_WbH;                    // overlay (phase 2): [16][68]
    float* s_W2TL = s_WbL;                    // overlay (phase 2): [16][68]
    __shared__ float s_q[NE], s_cb[NH1];
    __shared__ float s_m1[NH1], s_r1[NH1], s_a1[NH1], s_b2[NH2];
    __shared__ float s_sum[NH2], s_sq[NH2];

    int bid = blockIdx.x, tid = threadIdx.x;
    int b = bid >> 1, half = bid & 1;
    int R0 = half ? 128 : 0;
    int ntile = half ? 5 : 8;

    if (tid < NE) {
        s_q[tid] = q[b*NE + tid];
        s_cb[tid] = b1[tid];
        float n = (float)NROWS;
        float m = g_sum1[tid] / n;
        float v = g_sq1[tid] / n - m*m;
        s_m1[tid] = m;
        s_r1[tid] = rsqrtf(v + 1e-8f);
        s_a1[tid] = alpha1[tid];
    }
    if (tid < NH2) { s_b2[tid] = b2[tid]; s_sum[tid] = 0.f; s_sq[tid] = 0.f; }
    __syncthreads();

    #pragma unroll
    for (int i = 0; i < 16; i++) {
        int idx = tid + 256*i;
        int e = idx >> 6, j = idx & 63;
        float w = W1[(64+e)*64 + j] - W1[(128+e)*64 + j] + s_q[e]*W1[(192+e)*64 + j];
        unsigned wh, wl; tf32_split(w, wh, wl);
        s_WbH[e*72 + j] = __uint_as_float(wh);
        s_WbL[e*72 + j] = __uint_as_float(wl);
    }
    {
        int j = tid & 63, part = tid >> 6;
        float acc = 0.f;
        #pragma unroll
        for (int i = 0; i < 16; i++) {
            int e = part*16 + i;
            acc += s_q[e] * (W1[e*64 + j] + W1[(128+e)*64 + j]);
        }
        atomicAdd(&s_cb[j], acc);
    }
    #pragma unroll
    for (int i = 0; i < 8; i++) {
        int f4 = tid + 256*i;
        int r = f4 >> 4, e0 = (f4 & 15) << 2;
        int t = R0 + r;
        float4 v = (t < NT) ? *(const float4*)&hist[((size_t)(b*NT + t))*NE + e0]
                            : make_float4(0.f, 0.f, 0.f, 0.f);
        *(float4*)&s_h[r*68 + e0] = v;
    }
    __syncthreads();

    int w = tid >> 5, lane = tid & 31, g = lane >> 2, tin = lane & 3;

    // Phase 1: x1 tile in regs (full 3xTF32) + dice1 applied in regs
    float xd[8][4];
    if (w < ntile) {
        float d[8][4];
        #pragma unroll
        for (int j = 0; j < 8; j++)
            #pragma unroll
            for (int u = 0; u < 4; u++) d[j][u] = 0.f;

        int arow = (16*w + g)*68;
        #pragma unroll
        for (int kt = 0; kt < 8; kt++) {
            int k0 = kt*8;
            float a0f = s_h[arow + k0 + tin];
            float a1f = s_h[arow + 8*68 + k0 + tin];
            float a2f = s_h[arow + k0 + tin + 4];
            float a3f = s_h[arow + 8*68 + k0 + tin + 4];
            unsigned ah0,ah1,ah2,ah3, al0,al1,al2,al3;
            tf32_split(a0f, ah0, al0); tf32_split(a1f, ah1, al1);
            tf32_split(a2f, ah2, al2); tf32_split(a3f, ah3, al3);
            int bbase = (k0 + tin)*72 + g;
            #pragma unroll
            for (int j = 0; j < 8; j++) {
                unsigned bh0 = __float_as_uint(s_WbH[bbase + j*8]);
                unsigned bh1 = __float_as_uint(s_WbH[bbase + 4*72 + j*8]);
                unsigned bl0 = __float_as_uint(s_WbL[bbase + j*8]);
                unsigned bl1 = __float_as_uint(s_WbL[bbase + 4*72 + j*8]);
                MMA_TF32(d[j], ah0,ah1,ah2,ah3, bh0,bh1);
                MMA_TF32(d[j], ah0,ah1,ah2,ah3, bl0,bl1);
                MMA_TF32(d[j], al0,al1,al2,al3, bh0,bh1);
            }
        }
        #pragma unroll
        for (int j = 0; j < 8; j++) {
            int c0 = j*8 + tin*2;
            float cb0 = s_cb[c0],  cb1 = s_cb[c0+1];
            float m0  = s_m1[c0],  m1v = s_m1[c0+1];
            float r0  = s_r1[c0],  r1v = s_r1[c0+1];
            float a0  = s_a1[c0],  a1v = s_a1[c0+1];
            #pragma unroll
            for (int u = 0; u < 4; u++) {
                float v = d[j][u] + ((u & 1) ? cb1 : cb0);
                float mm = (u & 1) ? m1v : m0;
                float rr = (u & 1) ? r1v : r0;
                float aa = (u & 1) ? a1v : a0;
                float xn = (v - mm) * rr;
                float p  = __fdividef(1.f, 1.f + __expf(-xn));
                xd[j][u] = v * (aa + (1.f - aa) * p);
            }
        }
    }
    __syncthreads();   // all reads of s_h / Wb planes complete

    // write diced x into s_h region; write W2 split planes into Wb region
    if (w < ntile) {
        int r0w = (16*w + g)*68, r1w = (16*w + g + 8)*68;
        #pragma unroll
        for (int j = 0; j < 8; j++) {
            int c0 = j*8 + tin*2;
            *(float2*)&s_h[r0w + c0] = make_float2(xd[j][0], xd[j][1]);
            *(float2*)&s_h[r1w + c0] = make_float2(xd[j][2], xd[j][3]);
        }
    }
    #pragma unroll
    for (int i = 0; i < 4; i++) {
        int idx = tid + 256*i;
        int k = idx >> 4, n = idx & 15;
        float wv = W2[idx];
        unsigned wh, wl; tf32_split(wv, wh, wl);
        s_W2TH[n*68 + k] = __uint_as_float(wh);
        s_W2TL[n*68 + k] = __uint_as_float(wl);
    }
    __syncthreads();

    // Phase 2: x2 = xd @ W2 + b2 (3xTF32) + stats2
    if (w < ntile) {
        float d2[2][4];
        #pragma unroll
        for (int n = 0; n < 2; n++)
            #pragma unroll
            for (int u = 0; u < 4; u++) d2[n][u] = 0.f;

        int arow = (16*w + g)*68;
        #pragma unroll
        for (int kt = 0; kt < 8; kt++) {
            int k0 = kt*8;
            float a0f = s_h[arow + k0 + tin];
            float a1f = s_h[arow + 8*68 + k0 + tin];
            float a2f = s_h[arow + k0 + tin + 4];
            float a3f = s_h[arow + 8*68 + k0 + tin + 4];
            unsigned ah0,ah1,ah2,ah3, al0,al1,al2,al3;
            tf32_split(a0f, ah0, al0); tf32_split(a1f, ah1, al1);
            tf32_split(a2f, ah2, al2); tf32_split(a3f, ah3, al3);
            #pragma unroll
            for (int n = 0; n < 2; n++) {
                int bbase = (n*8 + g)*68 + k0 + tin;
                unsigned bh0 = __float_as_uint(s_W2TH[bbase]);
                unsigned bh1 = __float_as_uint(s_W2TH[bbase + 4]);
                unsigned bl0 = __float_as_uint(s_W2TL[bbase]);
                unsigned bl1 = __float_as_uint(s_W2TL[bbase + 4]);
                MMA_TF32(d2[n], ah0,ah1,ah2,ah3, bh0,bh1);
                MMA_TF32(d2[n], ah0,ah1,ah2,ah3, bl0,bl1);
                MMA_TF32(d2[n], al0,al1,al2,al3, bh0,bh1);
            }
        }

        int rA = R0 + 16*w + g, rB = rA + 8;
        bool okB = (rB < NT);
        #pragma unroll
        for (int n = 0; n < 2; n++) {
            int c0 = n*8 + tin*2;
            float b0v = s_b2[c0], b1v = s_b2[c0+1];
            float v0 = d2[n][0] + b0v, v1 = d2[n][1] + b1v;
            float v2 = d2[n][2] + b0v, v3 = d2[n][3] + b1v;
            *(float2*)&g_x2[(size_t)(b*NT + rA)*16 + c0] = make_float2(v0, v1);
            float sc0 = v0, sc1 = v1, qc0 = v0*v0, qc1 = v1*v1;
            if (okB) {
                *(float2*)&g_x2[(size_t)(b*NT + rB)*16 + c0] = make_float2(v2, v3);
                sc0 += v2; sc1 += v3; qc0 += v2*v2; qc1 += v3*v3;
            }
            #pragma unroll
            for (int off = 4; off <= 16; off <<= 1) {
                sc0 += __shfl_xor_sync(0xffffffffu, sc0, off);
                sc1 += __shfl_xor_sync(0xffffffffu, sc1, off);
                qc0 += __shfl_xor_sync(0xffffffffu, qc0, off);
                qc1 += __shfl_xor_sync(0xffffffffu, qc1, off);
            }
            if (lane < 4) {
                atomicAdd(&s_sum[c0],   sc0); atomicAdd(&s_sum[c0+1], sc1);
                atomicAdd(&s_sq[c0],    qc0); atomicAdd(&s_sq[c0+1],  qc1);
            }
        }
    }
    __syncthreads();
    if (tid < NH2) {
        atomicAdd(&g_sum2[tid], s_sum[tid]);
        atomicAdd(&g_sq2[tid],  s_sq[tid]);
    }
}

// ---------------------------------------------------------------------------
// K3: dice2 -> mask -> softmax over T -> score @ hist (3xTF32 MMA) -> out
// Logits staged directly [h][t] pad 228 (conflict-free A loads); exp values
// pre-split into hi/lo planes during softmax.
// ---------------------------------------------------------------------------
__global__ __launch_bounds__(256, 4) void k_final(
    const float* __restrict__ hist, const int* __restrict__ lens,
    const float* __restrict__ alpha2, float* __restrict__ out)
{
    __shared__ __align__(16) float s_pH[16][228];
    __shared__ __align__(16) float s_pL[16][228];
    __shared__ __align__(16) float s_hist[64][72];
    __shared__ float s_inv[16];
    __shared__ float s_m2[16], s_r2[16], s_a2[16];

    int b = blockIdx.x, tid = threadIdx.x;
    if (tid < 16) {
        float n = (float)NROWS;
        float m = g_sum2[tid] / n;
        float v = g_sq2[tid] / n - m*m;
        s_m2[tid] = m;
        s_r2[tid] = rsqrtf(v + 1e-8f);
        s_a2[tid] = alpha2[tid];
    }
    __syncthreads();
    int len = lens[b];

    // stage logits with dice2 + mask into [h][t]
    #pragma unroll
    for (int i = 0; i < 4; i++) {
        int f4 = tid + 256*i;
        if (f4 < 800) {
            int r = f4 >> 2, h0 = (f4 & 3) << 2;
            float4 v = *(const float4*)&g_x2[(size_t)(b*NT + r)*16 + h0];
            float vv[4] = {v.x, v.y, v.z, v.w};
            #pragma unroll
            for (int u = 0; u < 4; u++) {
                int hh = h0 + u;
                float xn = (vv[u] - s_m2[hh]) * s_r2[hh];
                float p  = __fdividef(1.f, 1.f + __expf(-xn));
                float a  = s_a2[hh];
                float dd = vv[u] * (a + (1.f - a) * p);
                s_pH[hh][r] = (r < len) ? 1e-9f : dd;
            }
        }
    }
    __syncthreads();

    int w = tid >> 5, lane = tid & 31;
    // softmax: warp w handles h = 2w, 2w+1 over contiguous [h][t]
    #pragma unroll
    for (int hh = 0; hh < 2; hh++) {
        int h = 2*w + hh;
        float m = -1e30f;
        #pragma unroll
        for (int i = 0; i < 7; i++) {
            int t = lane + 32*i;
            if (t < NT) m = fmaxf(m, s_pH[h][t]);
        }
        #pragma unroll
        for (int off = 16; off >= 1; off >>= 1)
            m = fmaxf(m, __shfl_xor_sync(0xffffffffu, m, off));
        float s = 0.f;
        #pragma unroll
        for (int i = 0; i < 7; i++) {
            int t = lane + 32*i;
            if (t < NT) {
                float ev = __expf(s_pH[h][t] - m);
                unsigned eh, el; tf32_split(ev, eh, el);
                s_pH[h][t] = __uint_as_float(eh);
                s_pL[h][t] = __uint_as_float(el);
                s += ev;
            }
        }
        #pragma unroll
        for (int off = 16; off >= 1; off >>= 1)
            s += __shfl_xor_sync(0xffffffffu, s, off);
        if (lane == 0) s_inv[h] = __fdividef(1.f, s);
    }

    // out = (1/sum) * p[16x200] @ hist[200x64] via 3xTF32 MMA
    int gq = lane >> 2, tin = lane & 3;
    int n0 = w * 8;
    float d[4] = {0.f, 0.f, 0.f, 0.f};

    for (int ck = 0; ck < 4; ck++) {
        __syncthreads();
        int rows = (ck < 3) ? 64 : 8;
        for (int f4 = tid; f4 < rows*16; f4 += 256) {
            int r = f4 >> 4, e0 = (f4 & 15) << 2;
            *(float4*)&s_hist[r][e0] =
                *(const float4*)&hist[(size_t)(b*NT + ck*64 + r)*64 + e0];
        }
        __syncthreads();
        int kts = rows >> 3;
        for (int kt = 0; kt < kts; kt++) {
            int k0 = kt*8, gk = ck*64 + k0;
            unsigned ah0 = __float_as_uint(s_pH[gq][gk + tin]);
            unsigned ah1 = __float_as_uint(s_pH[gq+8][gk + tin]);
            unsigned ah2 = __float_as_uint(s_pH[gq][gk + tin + 4]);
            unsigned ah3 = __float_as_uint(s_pH[gq+8][gk + tin + 4]);
            unsigned al0 = __float_as_uint(s_pL[gq][gk + tin]);
            unsigned al1 = __float_as_uint(s_pL[gq+8][gk + tin]);
            unsigned al2 = __float_as_uint(s_pL[gq][gk + tin + 4]);
            unsigned al3 = __float_as_uint(s_pL[gq+8][gk + tin + 4]);
            float b0f = s_hist[k0 + tin][n0 + gq];
            float b1f = s_hist[k0 + tin + 4][n0 + gq];
            unsigned bh0,bl0,bh1,bl1;
            tf32_split(b0f, bh0, bl0); tf32_split(b1f, bh1, bl1);
            MMA_TF32(d, ah0,ah1,ah2,ah3, bh0,bh1);
            MMA_TF32(d, ah0,ah1,ah2,ah3, bl0,bl1);
            MMA_TF32(d, al0,al1,al2,al3, bh0,bh1);
        }
    }

    float i0 = s_inv[gq], i1 = s_inv[gq + 8];
    int e0 = n0 + tin*2;
    *(float2*)&out[(size_t)(b*NH2 + gq    )*NE + e0] = make_float2(d[0]*i0, d[1]*i0);
    *(float2*)&out[(size_t)(b*NH2 + gq + 8)*NE + e0] = make_float2(d[2]*i1, d[3]*i1);
}

extern "C" void kernel_launch(void* const* d_in, const int* in_sizes, int n_in,
                              void* d_out, int out_size)
{
    const float* q    = (const float*)d_in[0];
    const float* hist = (const float*)d_in[1];
    const int*   lens = (const int*)  d_in[2];
    const float* W1   = (const float*)d_in[3];
    const float* b1   = (const float*)d_in[4];
    const float* a1   = (const float*)d_in[5];
    const float* W2   = (const float*)d_in[6];
    const float* b2   = (const float*)d_in[7];
    const float* a2   = (const float*)d_in[8];
    float* out = (float*)d_out;

    const int dynS = (128*68 + 64*72) * 4;       // 53248 B
    const int dynF = (128*68 + 2*64*72) * 4;     // 71680 B
    static int s_attr_done = 0;
    if (!s_attr_done) {
        cudaFuncSetAttribute(k_stats1, cudaFuncAttributeMaxDynamicSharedMemorySize, dynS);
        cudaFuncSetAttribute(k_fused,  cudaFuncAttributeMaxDynamicSharedMemorySize, dynF);
        s_attr_done = 1;
    }

    k_zero<<<1, 64>>>();
    k_stats1<<<2*NB, 256, dynS>>>(q, hist, W1, b1);
    k_fused<<<2*NB, 256, dynF>>>(q, hist, W1, b1, W2, b2, a1);
    k_final<<<NB, 256>>>(hist, lens, a2, out);
}

// round 8
// speedup vs baseline: 1.1719x; 1.1719x over previous
#include <cuda_runtime.h>
#include <math.h>

#define NB   2048
#define NT   200
#define NE   64
#define NH1  64
#define NH2  16
#define NROWS (NB*NT)

// Scratch (device globals; no allocation allowed)
__device__ float g_x1[(size_t)NROWS * NH1];   // [B*T, 64]
__device__ float g_x2[(size_t)NROWS * NH2];   // [B*T, 16]
__device__ float g_sum1[NH1], g_sq1[NH1];
__device__ float g_sum2[NH2], g_sq2[NH2];

__device__ __forceinline__ unsigned tf32_of(float f) {
    unsigned r;
    asm("cvt.rna.tf32.f32 %0, %1;" : "=r"(r) : "f"(f));
    return r;
}
__device__ __forceinline__ void tf32_split(float a, unsigned& hi, unsigned& lo) {
    hi = tf32_of(a);
    lo = tf32_of(a - __uint_as_float(hi));
}

#define MMA_TF32(d, a0,a1,a2,a3, b0,b1) \
    asm("mma.sync.aligned.m16n8k8.row.col.f32.tf32.tf32.f32 " \
        "{%0,%1,%2,%3}, {%4,%5,%6,%7}, {%8,%9}, {%0,%1,%2,%3};" \
        : "+f"(d[0]), "+f"(d[1]), "+f"(d[2]), "+f"(d[3]) \
        : "r"(a0), "r"(a1), "r"(a2), "r"(a3), "r"(b0), "r"(b1))

__global__ void k_zero() {
    int i = threadIdx.x;
    if (i < NH1) { g_sum1[i] = 0.f; g_sq1[i] = 0.f; }
    if (i < NH2) { g_sum2[i] = 0.f; g_sq2[i] = 0.f; }
}

// ---------------------------------------------------------------------------
// Kernel A: x1 = h@Wb + cb (3xTF32), store x1, accumulate stats1.
// Wb packed as float4 (hiA,hiB,loA,loB) at ((n*4+tin)*36 + kt*4): one LDS.128
// per B fragment, conflict-free. Warp tile: 32 rows (a=2) x 32 cols (c=4).
// 2 blocks per batch (rows 0..127 / 128..199).
// ---------------------------------------------------------------------------
__global__ __launch_bounds__(256, 3) void k_gemm1(
    const float* __restrict__ q, const float* __restrict__ hist,
    const float* __restrict__ W1, const float* __restrict__ b1)
{
    extern __shared__ __align__(16) float dsm[];
    float* s_h   = dsm;                       // [128][68] fp32 hist rows
    float* s_WbP = dsm + 128*68;              // packed Wb: 64n * 4tin * 9f4
    __shared__ float s_q[NE], s_cb[NH1], s_sum[NH1], s_sq[NH1];

    int bid = blockIdx.x, tid = threadIdx.x;
    int b = bid >> 1, half = bid & 1;
    int R0 = half ? 128 : 0;

    if (tid < NE) {
        s_q[tid] = q[b*NE + tid];
        s_cb[tid] = b1[tid];
        s_sum[tid] = 0.f; s_sq[tid] = 0.f;
    }
    __syncthreads();

    // Build Wb, split, pack: (k -> kt=k>>3, tin=k&3, khalf=(k>>2)&1)
    #pragma unroll
    for (int i = 0; i < 16; i++) {
        int idx = tid + 256*i;
        int e = idx >> 6, j = idx & 63;
        float w = W1[(64+e)*64 + j] - W1[(128+e)*64 + j] + s_q[e]*W1[(192+e)*64 + j];
        unsigned wh, wl; tf32_split(w, wh, wl);
        int base = (j*4 + (e&3))*36 + ((e>>3)<<2) + ((e>>2)&1);
        s_WbP[base]     = __uint_as_float(wh);
        s_WbP[base + 2] = __uint_as_float(wl);
    }
    // cb partial sums: 4 parts x 64 j
    {
        int j = tid & 63, part = tid >> 6;
        float acc = 0.f;
        #pragma unroll
        for (int i = 0; i < 16; i++) {
            int e = part*16 + i;
            acc += s_q[e] * (W1[e*64 + j] + W1[(128+e)*64 + j]);
        }
        atomicAdd(&s_cb[j], acc);
    }
    // Stage hist rows R0..R0+127 (zeros past NT)
    #pragma unroll
    for (int i = 0; i < 8; i++) {
        int f4 = tid + 256*i;
        int r = f4 >> 4, e0 = (f4 & 15) << 2;
        int t = R0 + r;
        float4 v = (t < NT) ? *(const float4*)&hist[((size_t)(b*NT + t))*NE + e0]
                            : make_float4(0.f, 0.f, 0.f, 0.f);
        *(float4*)&s_h[r*68 + e0] = v;
    }
    __syncthreads();

    int w = tid >> 5, lane = tid & 31, g = lane >> 2, tin = lane & 3;
    int rg = w & 3, cg = w >> 2;            // rows rg*32, cols cg*32
    int rowbase = rg * 32;

    float d[2][4][4];
    #pragma unroll
    for (int mt = 0; mt < 2; mt++)
        #pragma unroll
        for (int j = 0; j < 4; j++)
            #pragma unroll
            for (int u = 0; u < 4; u++) d[mt][j][u] = 0.f;

    #pragma unroll
    for (int kt = 0; kt < 8; kt++) {
        int k0 = kt*8;
        unsigned ah[2][4], al[2][4];
        #pragma unroll
        for (int mt = 0; mt < 2; mt++) {
            int ar = (rowbase + mt*16 + g)*68 + k0 + tin;
            float a0f = s_h[ar];
            float a1f = s_h[ar + 8*68];
            float a2f = s_h[ar + 4];
            float a3f = s_h[ar + 8*68 + 4];
            tf32_split(a0f, ah[mt][0], al[mt][0]);
            tf32_split(a1f, ah[mt][1], al[mt][1]);
            tf32_split(a2f, ah[mt][2], al[mt][2]);
            tf32_split(a3f, ah[mt][3], al[mt][3]);
        }
        #pragma unroll
        for (int j = 0; j < 4; j++) {
            int n = cg*32 + j*8 + g;
            float4 bv = *(const float4*)&s_WbP[(n*4 + tin)*36 + kt*4];
            unsigned bh0 = __float_as_uint(bv.x), bh1 = __float_as_uint(bv.y);
            unsigned bl0 = __float_as_uint(bv.z), bl1 = __float_as_uint(bv.w);
            #pragma unroll
            for (int mt = 0; mt < 2; mt++) {
                MMA_TF32(d[mt][j], ah[mt][0],ah[mt][1],ah[mt][2],ah[mt][3], bh0,bh1);
                MMA_TF32(d[mt][j], ah[mt][0],ah[mt][1],ah[mt][2],ah[mt][3], bl0,bl1);
                MMA_TF32(d[mt][j], al[mt][0],al[mt][1],al[mt][2],al[mt][3], bh0,bh1);
            }
        }
    }

    // epilogue: bias, store x1, stats (guard pad rows; guards warp-uniform)
    #pragma unroll
    for (int mt = 0; mt < 2; mt++) {
        int base = R0 + rowbase + mt*16;
        bool okA = (base < NT);           // rows base..base+7 (base mult of 16)
        bool okB = (base + 8 < NT);
        if (okA) {
            int rA = base + g, rB = rA + 8;
            #pragma unroll
            for (int j = 0; j < 4; j++) {
                int c0 = cg*32 + j*8 + tin*2;
                float cb0 = s_cb[c0], cb1 = s_cb[c0+1];
                float v0 = d[mt][j][0] + cb0, v1 = d[mt][j][1] + cb1;
                float v2 = d[mt][j][2] + cb0, v3 = d[mt][j][3] + cb1;
                float sc0 = v0, sc1 = v1, qc0 = v0*v0, qc1 = v1*v1;
                *(float2*)&g_x1[(size_t)(b*NT + rA)*NH1 + c0] = make_float2(v0, v1);
                if (okB) {
                    *(float2*)&g_x1[(size_t)(b*NT + rB)*NH1 + c0] = make_float2(v2, v3);
                    sc0 += v2; sc1 += v3; qc0 += v2*v2; qc1 += v3*v3;
                }
                #pragma unroll
                for (int off = 4; off <= 16; off <<= 1) {
                    sc0 += __shfl_xor_sync(0xffffffffu, sc0, off);
                    sc1 += __shfl_xor_sync(0xffffffffu, sc1, off);
                    qc0 += __shfl_xor_sync(0xffffffffu, qc0, off);
                    qc1 += __shfl_xor_sync(0xffffffffu, qc1, off);
                }
                if (lane < 4) {
                    atomicAdd(&s_sum[c0],   sc0); atomicAdd(&s_sum[c0+1], sc1);
                    atomicAdd(&s_sq[c0],    qc0); atomicAdd(&s_sq[c0+1],  qc1);
                }
            }
        }
    }
    __syncthreads();
    if (tid < NH1) {
        atomicAdd(&g_sum1[tid], s_sum[tid]);
        atomicAdd(&g_sq1[tid],  s_sq[tid]);
    }
}

// ---------------------------------------------------------------------------
// Kernel B: x2 = dice1(x1) @ W2 + b2 (3xTF32) + stats2. fin1 folded in.
// W2 packed float4 like Wb. Warp tile: 32 rows x 8 cols. 128 rows/block.
// ---------------------------------------------------------------------------
__global__ __launch_bounds__(256, 4) void k_gemm2(
    const float* __restrict__ W2, const float* __restrict__ b2,
    const float* __restrict__ alpha1)
{
    __shared__ __align__(16) float s_x[128*68];     // fp32 dice1(x1) tile
    __shared__ __align__(16) float s_W2P[64*36];    // packed W2: 16n*4tin*9f4
    __shared__ float s_m1[64], s_r1[64], s_a1[64], s_b2[16];
    __shared__ float s_sum[16], s_sq[16];

    int tid = threadIdx.x;
    int row0 = blockIdx.x * 128;
    if (tid < 64) {
        float nn = (float)NROWS;
        float m = g_sum1[tid] / nn;
        float v = g_sq1[tid] / nn - m*m;
        s_m1[tid] = m;
        s_r1[tid] = rsqrtf(v + 1e-8f);
        s_a1[tid] = alpha1[tid];
    }
    if (tid < 16) { s_b2[tid] = b2[tid]; s_sum[tid] = 0.f; s_sq[tid] = 0.f; }
    #pragma unroll
    for (int i = 0; i < 4; i++) {
        int idx = tid + 256*i;
        int k = idx >> 4, n = idx & 15;
        float wv = W2[idx];
        unsigned wh, wl; tf32_split(wv, wh, wl);
        int base = (n*4 + (k&3))*36 + ((k>>3)<<2) + ((k>>2)&1);
        s_W2P[base]     = __uint_as_float(wh);
        s_W2P[base + 2] = __uint_as_float(wl);
    }
    __syncthreads();

    // stage 128x64 x1 tile with dice1 applied (batched LDGs)
    #pragma unroll
    for (int bt = 0; bt < 4; bt++) {
        float4 vr[2];
        int f4b = tid + 256*(bt*2);
        #pragma unroll
        for (int u = 0; u < 2; u++) {
            int f4 = f4b + 256*u;
            int r = f4 >> 4, e0 = (f4 & 15) << 2;
            vr[u] = *(const float4*)&g_x1[(size_t)(row0 + r)*64 + e0];
        }
        #pragma unroll
        for (int u = 0; u < 2; u++) {
            int f4 = f4b + 256*u;
            int r = f4 >> 4, e0 = (f4 & 15) << 2;
            float vv[4] = {vr[u].x, vr[u].y, vr[u].z, vr[u].w};
            #pragma unroll
            for (int uu = 0; uu < 4; uu++) {
                int j = e0 + uu;
                float xn = (vv[uu] - s_m1[j]) * s_r1[j];
                float p  = __fdividef(1.f, 1.f + __expf(-xn));
                float a  = s_a1[j];
                vv[uu] = vv[uu] * (a + (1.f - a) * p);
            }
            *(float4*)&s_x[r*68 + e0] = make_float4(vv[0], vv[1], vv[2], vv[3]);
        }
    }
    __syncthreads();

    int w = tid >> 5, lane = tid & 31, g = lane >> 2, tin = lane & 3;
    int rg = w & 3, cg = w >> 2;          // rows rg*32, cols cg*8
    int rowbase = rg * 32;

    float d[2][4];
    #pragma unroll
    for (int mt = 0; mt < 2; mt++)
        #pragma unroll
        for (int u = 0; u < 4; u++) d[mt][u] = 0.f;

    #pragma unroll
    for (int kt = 0; kt < 8; kt++) {
        int k0 = kt*8;
        unsigned ah[2][4], al[2][4];
        #pragma unroll
        for (int mt = 0; mt < 2; mt++) {
            int ar = (rowbase + mt*16 + g)*68 + k0 + tin;
            float a0f = s_x[ar];
            float a1f = s_x[ar + 8*68];
            float a2f = s_x[ar + 4];
            float a3f = s_x[ar + 8*68 + 4];
            tf32_split(a0f, ah[mt][0], al[mt][0]);
            tf32_split(a1f, ah[mt][1], al[mt][1]);
            tf32_split(a2f, ah[mt][2], al[mt][2]);
            tf32_split(a3f, ah[mt][3], al[mt][3]);
        }
        int n = cg*8 + g;
        float4 bv = *(const float4*)&s_W2P[(n*4 + tin)*36 + kt*4];
        unsigned bh0 = __float_as_uint(bv.x), bh1 = __float_as_uint(bv.y);
        unsigned bl0 = __float_as_uint(bv.z), bl1 = __float_as_uint(bv.w);
        #pragma unroll
        for (int mt = 0; mt < 2; mt++) {
            MMA_TF32(d[mt], ah[mt][0],ah[mt][1],ah[mt][2],ah[mt][3], bh0,bh1);
            MMA_TF32(d[mt], ah[mt][0],ah[mt][1],ah[mt][2],ah[mt][3], bl0,bl1);
            MMA_TF32(d[mt], al[mt][0],al[mt][1],al[mt][2],al[mt][3], bh0,bh1);
        }
    }

    #pragma unroll
    for (int mt = 0; mt < 2; mt++) {
        int rA = row0 + rowbase + mt*16 + g, rB = rA + 8;
        int c0 = cg*8 + tin*2;
        float b0v = s_b2[c0], b1v = s_b2[c0+1];
        float v0 = d[mt][0] + b0v, v1 = d[mt][1] + b1v;
        float v2 = d[mt][2] + b0v, v3 = d[mt][3] + b1v;
        *(float2*)&g_x2[(size_t)rA*16 + c0] = make_float2(v0, v1);
        *(float2*)&g_x2[(size_t)rB*16 + c0] = make_float2(v2, v3);
        float sc0 = v0 + v2, sc1 = v1 + v3;
        float qc0 = v0*v0 + v2*v2, qc1 = v1*v1 + v3*v3;
        #pragma unroll
        for (int off = 4; off <= 16; off <<= 1) {
            sc0 += __shfl_xor_sync(0xffffffffu, sc0, off);
            sc1 += __shfl_xor_sync(0xffffffffu, sc1, off);
            qc0 += __shfl_xor_sync(0xffffffffu, qc0, off);
            qc1 += __shfl_xor_sync(0xffffffffu, qc1, off);
        }
        if (lane < 4) {
            atomicAdd(&s_sum[c0],   sc0); atomicAdd(&s_sum[c0+1], sc1);
            atomicAdd(&s_sq[c0],    qc0); atomicAdd(&s_sq[c0+1],  qc1);
        }
    }
    __syncthreads();
    if (tid < 16) {
        atomicAdd(&g_sum2[tid], s_sum[tid]);
        atomicAdd(&g_sq2[tid],  s_sq[tid]);
    }
}

// ---------------------------------------------------------------------------
// Kernel C: dice2 -> mask -> softmax -> score @ hist (3xTF32 MMA) -> out
// Logits staged [h][t] pad 228; exp pre-split into hi/lo planes.
// ---------------------------------------------------------------------------
__global__ __launch_bounds__(256, 4) void k_final(
    const float* __restrict__ hist, const int* __restrict__ lens,
    const float* __restrict__ alpha2, float* __restrict__ out)
{
    __shared__ __align__(16) float s_pH[16][228];
    __shared__ __align__(16) float s_pL[16][228];
    __shared__ __align__(16) float s_hist[64][72];
    __shared__ float s_inv[16];
    __shared__ float s_m2[16], s_r2[16], s_a2[16];

    int b = blockIdx.x, tid = threadIdx.x;
    if (tid < 16) {
        float nn = (float)NROWS;
        float m = g_sum2[tid] / nn;
        float v = g_sq2[tid] / nn - m*m;
        s_m2[tid] = m;
        s_r2[tid] = rsqrtf(v + 1e-8f);
        s_a2[tid] = alpha2[tid];
    }
    __syncthreads();
    int len = lens[b];

    // stage logits with dice2 + mask into [h][t]
    #pragma unroll
    for (int i = 0; i < 4; i++) {
        int f4 = tid + 256*i;
        if (f4 < 800) {
            int r = f4 >> 2, h0 = (f4 & 3) << 2;
            float4 v = *(const float4*)&g_x2[(size_t)(b*NT + r)*16 + h0];
            float vv[4] = {v.x, v.y, v.z, v.w};
            #pragma unroll
            for (int u = 0; u < 4; u++) {
                int hh = h0 + u;
                float xn = (vv[u] - s_m2[hh]) * s_r2[hh];
                float p  = __fdividef(1.f, 1.f + __expf(-xn));
                float a  = s_a2[hh];
                float dd = vv[u] * (a + (1.f - a) * p);
                s_pH[hh][r] = (r < len) ? 1e-9f : dd;
            }
        }
    }
    __syncthreads();

    int w = tid >> 5, lane = tid & 31;
    // softmax: warp w handles h = 2w, 2w+1
    #pragma unroll
    for (int hh = 0; hh < 2; hh++) {
        int h = 2*w + hh;
        float m = -1e30f;
        #pragma unroll
        for (int i = 0; i < 7; i++) {
            int t = lane + 32*i;
            if (t < NT) m = fmaxf(m, s_pH[h][t]);
        }
        #pragma unroll
        for (int off = 16; off >= 1; off >>= 1)
            m = fmaxf(m, __shfl_xor_sync(0xffffffffu, m, off));
        float s = 0.f;
        #pragma unroll
        for (int i = 0; i < 7; i++) {
            int t = lane + 32*i;
            if (t < NT) {
                float ev = __expf(s_pH[h][t] - m);
                unsigned eh, el; tf32_split(ev, eh, el);
                s_pH[h][t] = __uint_as_float(eh);
                s_pL[h][t] = __uint_as_float(el);
                s += ev;
            }
        }
        #pragma unroll
        for (int off = 16; off >= 1; off >>= 1)
            s += __shfl_xor_sync(0xffffffffu, s, off);
        if (lane == 0) s_inv[h] = __fdividef(1.f, s);
    }

    // out = (1/sum) * p[16x200] @ hist[200x64] via 3xTF32 MMA
    int gq = lane >> 2, tin = lane & 3;
    int n0 = w * 8;
    float d[4] = {0.f, 0.f, 0.f, 0.f};

    for (int ck = 0; ck < 4; ck++) {
        __syncthreads();
        int rows = (ck < 3) ? 64 : 8;
        for (int f4 = tid; f4 < rows*16; f4 += 256) {
            int r = f4 >> 4, e0 = (f4 & 15) << 2;
            *(float4*)&s_hist[r][e0] =
                *(const float4*)&hist[(size_t)(b*NT + ck*64 + r)*64 + e0];
        }
        __syncthreads();
        int kts = rows >> 3;
        for (int kt = 0; kt < kts; kt++) {
            int k0 = kt*8, gk = ck*64 + k0;
            unsigned ah0 = __float_as_uint(s_pH[gq][gk + tin]);
            unsigned ah1 = __float_as_uint(s_pH[gq+8][gk + tin]);
            unsigned ah2 = __float_as_uint(s_pH[gq][gk + tin + 4]);
            unsigned ah3 = __float_as_uint(s_pH[gq+8][gk + tin + 4]);
            unsigned al0 = __float_as_uint(s_pL[gq][gk + tin]);
            unsigned al1 = __float_as_uint(s_pL[gq+8][gk + tin]);
            unsigned al2 = __float_as_uint(s_pL[gq][gk + tin + 4]);
            unsigned al3 = __float_as_uint(s_pL[gq+8][gk + tin + 4]);
            float b0f = s_hist[k0 + tin][n0 + gq];
            float b1f = s_hist[k0 + tin + 4][n0 + gq];
            unsigned bh0,bl0,bh1,bl1;
            tf32_split(b0f, bh0, bl0); tf32_split(b1f, bh1, bl1);
            MMA_TF32(d, ah0,ah1,ah2,ah3, bh0,bh1);
            MMA_TF32(d, ah0,ah1,ah2,ah3, bl0,bl1);
            MMA_TF32(d, al0,al1,al2,al3, bh0,bh1);
        }
    }

    float i0 = s_inv[gq], i1 = s_inv[gq + 8];
    int e0 = n0 + tin*2;
    *(float2*)&out[(size_t)(b*NH2 + gq    )*NE + e0] = make_float2(d[0]*i0, d[1]*i0);
    *(float2*)&out[(size_t)(b*NH2 + gq + 8)*NE + e0] = make_float2(d[2]*i1, d[3]*i1);
}

extern "C" void kernel_launch(void* const* d_in, const int* in_sizes, int n_in,
                              void* d_out, int out_size)
{
    const float* q    = (const float*)d_in[0];
    const float* hist = (const float*)d_in[1];
    const int*   lens = (const int*)  d_in[2];
    const float* W1   = (const float*)d_in[3];
    const float* b1   = (const float*)d_in[4];
    const float* a1   = (const float*)d_in[5];
    const float* W2   = (const float*)d_in[6];
    const float* b2   = (const float*)d_in[7];
    const float* a2   = (const float*)d_in[8];
    float* out = (float*)d_out;

    const int dyn1 = (128*68 + 64*144) * 4;   // 71680 B
    static int s_attr_done = 0;
    if (!s_attr_done) {
        cudaFuncSetAttribute(k_gemm1, cudaFuncAttributeMaxDynamicSharedMemorySize, dyn1);
        s_attr_done = 1;
    }

    k_zero<<<1, 64>>>();
    k_gemm1<<<2*NB, 256, dyn1>>>(q, hist, W1, b1);
    k_gemm2<<<NROWS/128, 256>>>(W2, b2, a1);
    k_final<<<NB, 256>>>(hist, lens, a2, out);
}